// round 1
// baseline (speedup 1.0000x reference)
#include <cuda_runtime.h>
#include <math_constants.h>
#include <cstddef>

#define BATCH 16
#define TQ 800
#define TK 200

// Scratch (device-global: no allocations allowed)
__device__ float g_kh1 [BATCH * 1024 * TK];  // keys hidden (relu(conv1))
__device__ float g_kenc[BATCH * 80   * TK];  // keys_enc
__device__ float g_qh1 [BATCH * 160  * TQ];  // relu(q conv1)
__device__ float g_qh2 [BATCH * 80   * TQ];  // relu(q conv2)
__device__ float g_qenc[BATCH * 80   * TQ];  // queries_enc

// ---------------------------------------------------------------------------
// Generic conv1d (SAME padding, stride 1) as a tiled GEMM.
//   A = W   : (COUT, CIN*KW)   -- rows contiguous in memory already
//   B = im2col(x) over flattened n = b*T + t  (zero waste for T=200/800)
// Tile: BM=64 (cout) x BN=64 (n) x BK=16, 256 threads, 4x4 microtile.
// ---------------------------------------------------------------------------
template<int CIN, int COUT, int KW, int T, bool RELU>
__global__ __launch_bounds__(256, 4)
void conv1d_gemm(const float* __restrict__ x, const float* __restrict__ W,
                 const float* __restrict__ bias, float* __restrict__ y)
{
    constexpr int PAD = (KW - 1) / 2;
    constexpr int K   = CIN * KW;     // all shapes here are multiples of 16
    constexpr int BM = 64, BN = 64, BK = 16;

    __shared__ float As[BK][BM];   // transposed: contiguous in cout
    __shared__ float Bs[BK][BN];

    const int tid = threadIdx.x;
    const int n0  = blockIdx.x * BN;
    const int m0  = blockIdx.y * BM;

    const int a_co = tid >> 2;            // 0..63
    const int a_k4 = (tid & 3) << 2;      // 0,4,8,12
    const int b_kk = tid >> 4;            // 0..15
    const int b_n  = (tid & 15) << 2;     // 0..60
    const int tx   = tid & 15;            // n microtile
    const int ty   = tid >> 4;            // m microtile

    float acc[4][4];
    #pragma unroll
    for (int i = 0; i < 4; i++)
        #pragma unroll
        for (int j = 0; j < 4; j++) acc[i][j] = 0.f;

    const int  a_row = m0 + a_co;
    const bool a_ok  = (a_row < COUT);
    const float* aptr = W + (size_t)a_row * K;

    for (int k0 = 0; k0 < K; k0 += BK) {
        // --- load A tile (weights), transposed into smem ---
        float4 av = make_float4(0.f, 0.f, 0.f, 0.f);
        if (a_ok) av = *reinterpret_cast<const float4*>(aptr + k0 + a_k4);
        As[a_k4 + 0][a_co] = av.x;
        As[a_k4 + 1][a_co] = av.y;
        As[a_k4 + 2][a_co] = av.z;
        As[a_k4 + 3][a_co] = av.w;

        // --- load B tile (im2col gather with zero padding) ---
        {
            const int kkg = k0 + b_kk;
            const int ci  = kkg / KW;
            const int w   = kkg % KW;
            #pragma unroll
            for (int j = 0; j < 4; j++) {
                const int n  = n0 + b_n + j;
                const int bb = n / T;
                const int t  = n - bb * T;
                const int tg = t + w - PAD;
                float v = 0.f;
                if (tg >= 0 && tg < T)
                    v = x[((size_t)bb * CIN + ci) * T + tg];
                Bs[b_kk][b_n + j] = v;
            }
        }
        __syncthreads();

        #pragma unroll
        for (int kk = 0; kk < BK; kk++) {
            const float4 a4 = *reinterpret_cast<const float4*>(&As[kk][ty << 2]);
            const float4 b4 = *reinterpret_cast<const float4*>(&Bs[kk][tx << 2]);
            const float aa[4] = {a4.x, a4.y, a4.z, a4.w};
            const float bb[4] = {b4.x, b4.y, b4.z, b4.w};
            #pragma unroll
            for (int i = 0; i < 4; i++)
                #pragma unroll
                for (int j = 0; j < 4; j++)
                    acc[i][j] = fmaf(aa[i], bb[j], acc[i][j]);
        }
        __syncthreads();
    }

    // --- epilogue: bias (+relu) and scatter back to (b, co, t) layout ---
    #pragma unroll
    for (int i = 0; i < 4; i++) {
        const int co = m0 + (ty << 2) + i;
        if (co < COUT) {
            const float bv = bias[co];
            #pragma unroll
            for (int j = 0; j < 4; j++) {
                const int n  = n0 + (tx << 2) + j;
                const int bb = n / T;
                const int t  = n - bb * T;
                float v = acc[i][j] + bv;
                if (RELU) v = fmaxf(v, 0.f);
                y[((size_t)bb * COUT + co) * T + t] = v;
            }
        }
    }
}

// ---------------------------------------------------------------------------
// Fused attention: scores + log_softmax + log(prior) + mask + softmax.
// One block per (b, 32-query tile). keys_enc[b] (80x200) lives in smem.
// q2 cancels under both softmaxes, so it is never computed.
// ---------------------------------------------------------------------------
static __device__ __forceinline__ float warp_max(float v) {
    #pragma unroll
    for (int o = 16; o > 0; o >>= 1) v = fmaxf(v, __shfl_xor_sync(0xffffffffu, v, o));
    return v;
}
static __device__ __forceinline__ float warp_sum(float v) {
    #pragma unroll
    for (int o = 16; o > 0; o >>= 1) v += __shfl_xor_sync(0xffffffffu, v, o);
    return v;
}

__global__ __launch_bounds__(256)
void attn_kernel(const float* __restrict__ qenc, const float* __restrict__ kenc,
                 const float* __restrict__ prior, const unsigned char* __restrict__ mask,
                 float* __restrict__ attn_out, float* __restrict__ logp_out)
{
    extern __shared__ float sm[];
    float* Ks  = sm;                 // 80*200
    float* Qs  = sm + 80 * TK;       // 32*81 (padded to kill store conflicts)
    float* k2s = Qs + 32 * 81;       // 200

    const int b   = blockIdx.y;
    const int q0  = blockIdx.x * 32;
    const int tid = threadIdx.x;

    // load keys_enc[b] into smem (float4 bulk copy: 16000 floats)
    const float* kb = kenc + (size_t)b * 80 * TK;
    for (int i = tid; i < 80 * TK / 4; i += 256)
        reinterpret_cast<float4*>(Ks)[i] = reinterpret_cast<const float4*>(kb)[i];

    // load 32 query columns, transposed: Qs[q_local][c]
    const float* qb = qenc + (size_t)b * 80 * TQ;
    {
        const int ql = tid & 31;
        for (int c = tid >> 5; c < 80; c += 8)
            Qs[ql * 81 + c] = qb[c * TQ + q0 + ql];
    }
    __syncthreads();

    // k2[k] = sum_c K[c][k]^2
    for (int k = tid; k < TK; k += 256) {
        float s = 0.f;
        #pragma unroll 8
        for (int c = 0; c < 80; c++) { const float v = Ks[c * TK + k]; s = fmaf(v, v, s); }
        k2s[k] = s;
    }
    __syncthreads();

    const int warp = tid >> 5, lane = tid & 31;
    constexpr int KI = 7;  // ceil(200/32)

    // qk dot products: 4 rows/warp x 7 k's/lane, reusing Ks reads across rows
    float s[4][KI];
    #pragma unroll
    for (int r = 0; r < 4; r++)
        #pragma unroll
        for (int i = 0; i < KI; i++) s[r][i] = 0.f;

    for (int c = 0; c < 80; c++) {
        float qv[4];
        #pragma unroll
        for (int r = 0; r < 4; r++) qv[r] = Qs[(warp * 4 + r) * 81 + c];
        float kv[KI];
        #pragma unroll
        for (int i = 0; i < 6; i++) kv[i] = Ks[c * TK + lane + 32 * i];
        kv[6] = (lane < 8) ? Ks[c * TK + lane + 192] : 0.f;
        #pragma unroll
        for (int r = 0; r < 4; r++)
            #pragma unroll
            for (int i = 0; i < KI; i++)
                s[r][i] = fmaf(qv[r], kv[i], s[r][i]);
    }

    const float NEG_INF = -CUDART_INF_F;
    #pragma unroll
    for (int r = 0; r < 4; r++) {
        const int q = q0 + warp * 4 + r;
        const size_t row = ((size_t)b * TQ + q) * TK;

        // scores (q2 omitted: shift-invariant under softmax/log_softmax)
        float m1 = NEG_INF;
        #pragma unroll
        for (int i = 0; i < KI; i++) {
            const int k = lane + 32 * i;
            const float sc = (k < TK) ? -5e-4f * (k2s[k] - 2.f * s[r][i]) : NEG_INF;
            s[r][i] = sc;
            m1 = fmaxf(m1, sc);
        }
        m1 = warp_max(m1);
        float se = 0.f;
        #pragma unroll
        for (int i = 0; i < KI; i++) {
            const int k = lane + 32 * i;
            if (k < TK) se += __expf(s[r][i] - m1);
        }
        se = warp_sum(se);
        const float lse = m1 + __logf(se);

        // logprob = log_softmax + log(prior + 1e-8); then masked softmax
        float m2 = NEG_INF;
        #pragma unroll
        for (int i = 0; i < KI; i++) {
            const int k = lane + 32 * i;
            if (k < TK) {
                const float lp = s[r][i] - lse + __logf(prior[row + k] + 1e-8f);
                logp_out[row + k] = lp;
                const float t = mask[b * TK + k] ? NEG_INF : lp;
                s[r][i] = t;
                m2 = fmaxf(m2, t);
            }
        }
        m2 = warp_max(m2);
        float se2 = 0.f;
        float e[KI];
        #pragma unroll
        for (int i = 0; i < KI; i++) {
            const int k = lane + 32 * i;
            if (k < TK) { e[i] = __expf(s[r][i] - m2); se2 += e[i]; }
        }
        se2 = warp_sum(se2);
        const float inv = 1.f / se2;
        #pragma unroll
        for (int i = 0; i < KI; i++) {
            const int k = lane + 32 * i;
            if (k < TK) attn_out[row + k] = e[i] * inv;
        }
    }
}

// ---------------------------------------------------------------------------
extern "C" void kernel_launch(void* const* d_in, const int* in_sizes, int n_in,
                              void* d_out, int out_size)
{
    const float* queries = (const float*)d_in[0];
    const float* keys    = (const float*)d_in[1];
    // d_in[2] = query_lens (unused by the reference computation)
    const unsigned char* mask = (const unsigned char*)d_in[3];
    const float* prior   = (const float*)d_in[4];
    const float* kW1 = (const float*)d_in[5];
    const float* kb1 = (const float*)d_in[6];
    const float* kW2 = (const float*)d_in[7];
    const float* kb2 = (const float*)d_in[8];
    const float* qW1 = (const float*)d_in[9];
    const float* qb1 = (const float*)d_in[10];
    const float* qW2 = (const float*)d_in[11];
    const float* qb2 = (const float*)d_in[12];
    const float* qW3 = (const float*)d_in[13];
    const float* qb3 = (const float*)d_in[14];

    float* out      = (float*)d_out;
    float* attn_out = out;                               // tuple elem 0
    float* logp_out = out + (size_t)BATCH * TQ * TK;     // tuple elem 1

    float *kh1, *kenc, *qh1, *qh2, *qenc;
    cudaGetSymbolAddress((void**)&kh1,  g_kh1);
    cudaGetSymbolAddress((void**)&kenc, g_kenc);
    cudaGetSymbolAddress((void**)&qh1,  g_qh1);
    cudaGetSymbolAddress((void**)&qh2,  g_qh2);
    cudaGetSymbolAddress((void**)&qenc, g_qenc);

    // keys path: conv(512->1024,k3)+relu, then conv(1024->80,k1)
    conv1d_gemm<512, 1024, 3, TK, true ><<<dim3(BATCH * TK / 64, 1024 / 64), 256>>>(keys, kW1, kb1, kh1);
    conv1d_gemm<1024,  80, 1, TK, false><<<dim3(BATCH * TK / 64, 2),         256>>>(kh1,  kW2, kb2, kenc);

    // queries path: conv(80->160,k3)+relu, conv(160->80,k1)+relu, conv(80->80,k1)
    conv1d_gemm<80,  160, 3, TQ, true ><<<dim3(BATCH * TQ / 64, 3), 256>>>(queries, qW1, qb1, qh1);
    conv1d_gemm<160,  80, 1, TQ, true ><<<dim3(BATCH * TQ / 64, 2), 256>>>(qh1,     qW2, qb2, qh2);
    conv1d_gemm<80,   80, 1, TQ, false><<<dim3(BATCH * TQ / 64, 2), 256>>>(qh2,     qW3, qb3, qenc);

    // fused attention (75168 B dynamic smem)
    const int smem = (80 * TK + 32 * 81 + TK) * (int)sizeof(float);
    cudaFuncSetAttribute(attn_kernel, cudaFuncAttributeMaxDynamicSharedMemorySize, smem);
    attn_kernel<<<dim3(TQ / 32, BATCH), 256, smem>>>(qenc, kenc, prior, mask, attn_out, logp_out);
}

// round 3
// speedup vs baseline: 1.8121x; 1.8121x over previous
#include <cuda_runtime.h>
#include <cuda_bf16.h>
#include <math_constants.h>
#include <cstdint>
#include <cstddef>

#define BATCH 16
#define TQ 800
#define TK 200

// Scratch (device-global: no allocations allowed)
__device__ float g_kh1 [BATCH * 1024 * TK];  // keys hidden (relu(conv1))
__device__ float g_kenc[BATCH * 80   * TK];  // keys_enc
__device__ float g_qh1 [BATCH * 160  * TQ];  // relu(q conv1)
__device__ float g_qh2 [BATCH * 80   * TQ];  // relu(q conv2)
__device__ float g_qenc[BATCH * 80   * TQ];  // queries_enc

__device__ __forceinline__ uint32_t smem_to_u32(const void* p) {
    uint32_t a;
    asm("{ .reg .u64 t; cvta.to.shared.u64 t, %1; cvt.u32.u64 %0, t; }" : "=r"(a) : "l"(p));
    return a;
}

// ldmatrix x4 (four 8x8 b16 matrices)
__device__ __forceinline__ void ldsm_x4(uint32_t& r0, uint32_t& r1, uint32_t& r2, uint32_t& r3,
                                        uint32_t addr) {
    asm volatile("ldmatrix.sync.aligned.m8n8.x4.shared.b16 {%0,%1,%2,%3}, [%4];"
                 : "=r"(r0), "=r"(r1), "=r"(r2), "=r"(r3) : "r"(addr));
}
// mma m16n8k16 row.col f32 <- bf16 x bf16 + f32
__device__ __forceinline__ void mma_bf16(float* c, uint32_t a0, uint32_t a1, uint32_t a2, uint32_t a3,
                                         uint32_t b0, uint32_t b1) {
    asm volatile("mma.sync.aligned.m16n8k16.row.col.f32.bf16.bf16.f32 "
                 "{%0,%1,%2,%3}, {%4,%5,%6,%7}, {%8,%9}, {%0,%1,%2,%3};"
                 : "+f"(c[0]), "+f"(c[1]), "+f"(c[2]), "+f"(c[3])
                 : "r"(a0), "r"(a1), "r"(a2), "r"(a3), "r"(b0), "r"(b1));
}

// ===========================================================================
// keys conv1 (512 -> 1024, k=3, T=200) as mma.sync bf16 GEMM.
//   M = 1024 (cout), K = 1536 (ci*3+w), N = 3200 (b*200+t)
//   CTA tile 128(M) x 64(N), BK=64. 8 warps as 4(M) x 2(N); warp tile 32x32.
//   Smem rows padded to 72 bf16 (144B) -> conflict-free ldmatrix.
// ===========================================================================
#define C1_CIN  512
#define C1_COUT 1024
#define C1_K    1536
#define C1_BK   64
#define C1_NCHUNK (C1_K / C1_BK)   // 24
#define C1_LDA  72                 // bf16 elements per padded row
#define C1_LDB  72

__global__ __launch_bounds__(256, 2)
void conv1_mma(const float* __restrict__ x, const float* __restrict__ W,
               const float* __restrict__ bias, float* __restrict__ y)
{
    __shared__ __nv_bfloat16 As[128 * C1_LDA];  // 18432 B
    __shared__ __nv_bfloat16 Bs[64  * C1_LDB];  //  9216 B

    const int tid  = threadIdx.x;
    const int wid  = tid >> 5;
    const int lane = tid & 31;
    const int m0 = blockIdx.y * 128;
    const int n0 = blockIdx.x * 64;

    const int warp_m = wid >> 1;     // 0..3 -> 32 rows each
    const int warp_n = wid & 1;      // 0..1 -> 32 cols each

    const uint32_t As_base = smem_to_u32(As);
    const uint32_t Bs_base = smem_to_u32(Bs);

    float acc[2][4][4];
    #pragma unroll
    for (int mt = 0; mt < 2; mt++)
        #pragma unroll
        for (int nt = 0; nt < 4; nt++)
            #pragma unroll
            for (int i = 0; i < 4; i++) acc[mt][nt][i] = 0.f;

    // ldmatrix source addresses (fixed per lane; k-step offset added in loop)
    // A: row = warp_m*32 + mt*16 + (lane&15), k-col byte = ((lane>>4)*8)*2
    // B: row = warp_n*32 + np*16 + (lane&15), same k pattern
    const int a_row = warp_m * 32 + (lane & 15);
    const int b_row = warp_n * 32 + (lane & 15);
    const uint32_t a_addr0 = As_base + (a_row * C1_LDA + (lane >> 4) * 8) * 2;
    const uint32_t b_addr0 = Bs_base + (b_row * C1_LDB + (lane >> 4) * 8) * 2;

    for (int ch = 0; ch < C1_NCHUNK; ch++) {
        const int k0 = ch * C1_BK;
        __syncthreads();   // previous compute done before overwrite

        // --- A: 128 rows x 64 k, float2 -> bf16x2 ---
        #pragma unroll
        for (int j = 0; j < 16; j++) {
            const int p  = tid + 256 * j;     // 4096 float2
            const int r  = p >> 5;            // 0..127
            const int k2 = (p & 31) << 1;     // even k
            const float2 v = *reinterpret_cast<const float2*>(
                W + (size_t)(m0 + r) * C1_K + k0 + k2);
            __nv_bfloat162 b2 = __float22bfloat162_rn(v);
            *reinterpret_cast<uint32_t*>(&As[r * C1_LDA + k2]) = *reinterpret_cast<uint32_t*>(&b2);
        }
        // --- B: 64 rows (n) x 64 k im2col gather ---
        #pragma unroll
        for (int j = 0; j < 16; j++) {
            const int e  = tid + 256 * j;     // 4096 elements
            const int r  = e >> 6;            // n local
            const int k  = e & 63;
            const int kk = k0 + k;
            const int ci = kk / 3;
            const int w  = kk - ci * 3;
            const int n  = n0 + r;
            const int bb = n / TK;
            const int t  = n - bb * TK;
            const int tg = t + w - 1;
            float v = 0.f;
            if (tg >= 0 && tg < TK) v = x[((size_t)bb * C1_CIN + ci) * TK + tg];
            Bs[r * C1_LDB + k] = __float2bfloat16_rn(v);
        }
        __syncthreads();

        #pragma unroll
        for (int ks = 0; ks < 4; ks++) {      // 4 x k16 per chunk
            const uint32_t koff = ks * 16 * 2;  // bytes
            uint32_t a[2][4], b[2][4];
            #pragma unroll
            for (int mt = 0; mt < 2; mt++)
                ldsm_x4(a[mt][0], a[mt][1], a[mt][2], a[mt][3],
                        a_addr0 + mt * 16 * C1_LDA * 2 + koff);
            #pragma unroll
            for (int np = 0; np < 2; np++)    // each x4 covers two n8 subtiles
                ldsm_x4(b[np][0], b[np][1], b[np][2], b[np][3],
                        b_addr0 + np * 16 * C1_LDB * 2 + koff);
            #pragma unroll
            for (int mt = 0; mt < 2; mt++) {
                #pragma unroll
                for (int np = 0; np < 2; np++) {
                    // subtile n = np*16 + 0..7 : fragments (b[np][0], b[np][2])
                    mma_bf16(acc[mt][np * 2 + 0], a[mt][0], a[mt][1], a[mt][2], a[mt][3],
                             b[np][0], b[np][2]);
                    // subtile n = np*16 + 8..15 : fragments (b[np][1], b[np][3])
                    mma_bf16(acc[mt][np * 2 + 1], a[mt][0], a[mt][1], a[mt][2], a[mt][3],
                             b[np][1], b[np][3]);
                }
            }
        }
    }

    // Epilogue: bias + relu, scalar stores (tiles cross batch boundaries in n)
    #pragma unroll
    for (int mt = 0; mt < 2; mt++) {
        const int m_base = m0 + warp_m * 32 + mt * 16 + (lane >> 2);
        const float bv0 = bias[m_base];
        const float bv1 = bias[m_base + 8];
        #pragma unroll
        for (int nt = 0; nt < 4; nt++) {
            const int n_base = n0 + warp_n * 32 + nt * 8 + ((lane & 3) << 1);
            #pragma unroll
            for (int cc = 0; cc < 2; cc++) {
                const int n  = n_base + cc;
                const int bb = n / TK;
                const int t  = n - bb * TK;
                const size_t base = ((size_t)bb * C1_COUT) * TK + t;
                y[base + (size_t)m_base * TK] =
                    fmaxf(acc[mt][nt][cc] + bv0, 0.f);
                y[base + (size_t)(m_base + 8) * TK] =
                    fmaxf(acc[mt][nt][2 + cc] + bv1, 0.f);
            }
        }
    }
}

// ---------------------------------------------------------------------------
// Generic conv1d (SAME padding, stride 1) as a tiled FFMA GEMM (small shapes).
// ---------------------------------------------------------------------------
template<int CIN, int COUT, int KW, int T, bool RELU>
__global__ __launch_bounds__(256, 4)
void conv1d_gemm(const float* __restrict__ x, const float* __restrict__ W,
                 const float* __restrict__ bias, float* __restrict__ y)
{
    constexpr int PAD = (KW - 1) / 2;
    constexpr int K   = CIN * KW;
    constexpr int BM = 64, BN = 64, BK = 16;

    __shared__ float As[BK][BM];
    __shared__ float Bs[BK][BN];

    const int tid = threadIdx.x;
    const int n0  = blockIdx.x * BN;
    const int m0  = blockIdx.y * BM;

    const int a_co = tid >> 2;
    const int a_k4 = (tid & 3) << 2;
    const int b_kk = tid >> 4;
    const int b_n  = (tid & 15) << 2;
    const int tx   = tid & 15;
    const int ty   = tid >> 4;

    float acc[4][4];
    #pragma unroll
    for (int i = 0; i < 4; i++)
        #pragma unroll
        for (int j = 0; j < 4; j++) acc[i][j] = 0.f;

    const int  a_row = m0 + a_co;
    const bool a_ok  = (a_row < COUT);
    const float* aptr = W + (size_t)a_row * K;

    for (int k0 = 0; k0 < K; k0 += BK) {
        float4 av = make_float4(0.f, 0.f, 0.f, 0.f);
        if (a_ok) av = *reinterpret_cast<const float4*>(aptr + k0 + a_k4);
        As[a_k4 + 0][a_co] = av.x;
        As[a_k4 + 1][a_co] = av.y;
        As[a_k4 + 2][a_co] = av.z;
        As[a_k4 + 3][a_co] = av.w;
        {
            const int kkg = k0 + b_kk;
            const int ci  = kkg / KW;
            const int w   = kkg % KW;
            #pragma unroll
            for (int j = 0; j < 4; j++) {
                const int n  = n0 + b_n + j;
                const int bb = n / T;
                const int t  = n - bb * T;
                const int tg = t + w - PAD;
                float v = 0.f;
                if (tg >= 0 && tg < T)
                    v = x[((size_t)bb * CIN + ci) * T + tg];
                Bs[b_kk][b_n + j] = v;
            }
        }
        __syncthreads();

        #pragma unroll
        for (int kk = 0; kk < BK; kk++) {
            const float4 a4 = *reinterpret_cast<const float4*>(&As[kk][ty << 2]);
            const float4 b4 = *reinterpret_cast<const float4*>(&Bs[kk][tx << 2]);
            const float aa[4] = {a4.x, a4.y, a4.z, a4.w};
            const float bb[4] = {b4.x, b4.y, b4.z, b4.w};
            #pragma unroll
            for (int i = 0; i < 4; i++)
                #pragma unroll
                for (int j = 0; j < 4; j++)
                    acc[i][j] = fmaf(aa[i], bb[j], acc[i][j]);
        }
        __syncthreads();
    }

    #pragma unroll
    for (int i = 0; i < 4; i++) {
        const int co = m0 + (ty << 2) + i;
        if (co < COUT) {
            const float bv = bias[co];
            #pragma unroll
            for (int j = 0; j < 4; j++) {
                const int n  = n0 + (tx << 2) + j;
                const int bb = n / T;
                const int t  = n - bb * T;
                float v = acc[i][j] + bv;
                if (RELU) v = fmaxf(v, 0.f);
                y[((size_t)bb * COUT + co) * T + t] = v;
            }
        }
    }
}

// ---------------------------------------------------------------------------
// Fused attention (unchanged)
// ---------------------------------------------------------------------------
static __device__ __forceinline__ float warp_max(float v) {
    #pragma unroll
    for (int o = 16; o > 0; o >>= 1) v = fmaxf(v, __shfl_xor_sync(0xffffffffu, v, o));
    return v;
}
static __device__ __forceinline__ float warp_sum(float v) {
    #pragma unroll
    for (int o = 16; o > 0; o >>= 1) v += __shfl_xor_sync(0xffffffffu, v, o);
    return v;
}

__global__ __launch_bounds__(256)
void attn_kernel(const float* __restrict__ qenc, const float* __restrict__ kenc,
                 const float* __restrict__ prior, const unsigned char* __restrict__ mask,
                 float* __restrict__ attn_out, float* __restrict__ logp_out)
{
    extern __shared__ float sm[];
    float* Ks  = sm;
    float* Qs  = sm + 80 * TK;
    float* k2s = Qs + 32 * 81;

    const int b   = blockIdx.y;
    const int q0  = blockIdx.x * 32;
    const int tid = threadIdx.x;

    const float* kb = kenc + (size_t)b * 80 * TK;
    for (int i = tid; i < 80 * TK / 4; i += 256)
        reinterpret_cast<float4*>(Ks)[i] = reinterpret_cast<const float4*>(kb)[i];

    const float* qb = qenc + (size_t)b * 80 * TQ;
    {
        const int ql = tid & 31;
        for (int c = tid >> 5; c < 80; c += 8)
            Qs[ql * 81 + c] = qb[c * TQ + q0 + ql];
    }
    __syncthreads();

    for (int k = tid; k < TK; k += 256) {
        float s = 0.f;
        #pragma unroll 8
        for (int c = 0; c < 80; c++) { const float v = Ks[c * TK + k]; s = fmaf(v, v, s); }
        k2s[k] = s;
    }
    __syncthreads();

    const int warp = tid >> 5, lane = tid & 31;
    constexpr int KI = 7;

    float s[4][KI];
    #pragma unroll
    for (int r = 0; r < 4; r++)
        #pragma unroll
        for (int i = 0; i < KI; i++) s[r][i] = 0.f;

    for (int c = 0; c < 80; c++) {
        float qv[4];
        #pragma unroll
        for (int r = 0; r < 4; r++) qv[r] = Qs[(warp * 4 + r) * 81 + c];
        float kv[KI];
        #pragma unroll
        for (int i = 0; i < 6; i++) kv[i] = Ks[c * TK + lane + 32 * i];
        kv[6] = (lane < 8) ? Ks[c * TK + lane + 192] : 0.f;
        #pragma unroll
        for (int r = 0; r < 4; r++)
            #pragma unroll
            for (int i = 0; i < KI; i++)
                s[r][i] = fmaf(qv[r], kv[i], s[r][i]);
    }

    const float NEG_INF = -CUDART_INF_F;
    #pragma unroll
    for (int r = 0; r < 4; r++) {
        const int q = q0 + warp * 4 + r;
        const size_t row = ((size_t)b * TQ + q) * TK;

        float m1 = NEG_INF;
        #pragma unroll
        for (int i = 0; i < KI; i++) {
            const int k = lane + 32 * i;
            const float sc = (k < TK) ? -5e-4f * (k2s[k] - 2.f * s[r][i]) : NEG_INF;
            s[r][i] = sc;
            m1 = fmaxf(m1, sc);
        }
        m1 = warp_max(m1);
        float se = 0.f;
        #pragma unroll
        for (int i = 0; i < KI; i++) {
            const int k = lane + 32 * i;
            if (k < TK) se += __expf(s[r][i] - m1);
        }
        se = warp_sum(se);
        const float lse = m1 + __logf(se);

        float m2 = NEG_INF;
        #pragma unroll
        for (int i = 0; i < KI; i++) {
            const int k = lane + 32 * i;
            if (k < TK) {
                const float lp = s[r][i] - lse + __logf(prior[row + k] + 1e-8f);
                logp_out[row + k] = lp;
                const float t = mask[b * TK + k] ? NEG_INF : lp;
                s[r][i] = t;
                m2 = fmaxf(m2, t);
            }
        }
        m2 = warp_max(m2);
        float se2 = 0.f;
        float e[KI];
        #pragma unroll
        for (int i = 0; i < KI; i++) {
            const int k = lane + 32 * i;
            if (k < TK) { e[i] = __expf(s[r][i] - m2); se2 += e[i]; }
        }
        se2 = warp_sum(se2);
        const float inv = 1.f / se2;
        #pragma unroll
        for (int i = 0; i < KI; i++) {
            const int k = lane + 32 * i;
            if (k < TK) attn_out[row + k] = e[i] * inv;
        }
    }
}

// ---------------------------------------------------------------------------
extern "C" void kernel_launch(void* const* d_in, const int* in_sizes, int n_in,
                              void* d_out, int out_size)
{
    const float* queries = (const float*)d_in[0];
    const float* keys    = (const float*)d_in[1];
    const unsigned char* mask = (const unsigned char*)d_in[3];
    const float* prior   = (const float*)d_in[4];
    const float* kW1 = (const float*)d_in[5];
    const float* kb1 = (const float*)d_in[6];
    const float* kW2 = (const float*)d_in[7];
    const float* kb2 = (const float*)d_in[8];
    const float* qW1 = (const float*)d_in[9];
    const float* qb1 = (const float*)d_in[10];
    const float* qW2 = (const float*)d_in[11];
    const float* qb2 = (const float*)d_in[12];
    const float* qW3 = (const float*)d_in[13];
    const float* qb3 = (const float*)d_in[14];

    float* out      = (float*)d_out;
    float* attn_out = out;
    float* logp_out = out + (size_t)BATCH * TQ * TK;

    float *kh1, *kenc, *qh1, *qh2, *qenc;
    cudaGetSymbolAddress((void**)&kh1,  g_kh1);
    cudaGetSymbolAddress((void**)&kenc, g_kenc);
    cudaGetSymbolAddress((void**)&qh1,  g_qh1);
    cudaGetSymbolAddress((void**)&qh2,  g_qh2);
    cudaGetSymbolAddress((void**)&qenc, g_qenc);

    // keys conv1 (512->1024, k3) on tensor cores via mma.sync bf16
    conv1_mma<<<dim3(BATCH * TK / 64, C1_COUT / 128), 256>>>(keys, kW1, kb1, kh1);

    // keys conv2 (1024->80, pw)
    conv1d_gemm<1024,  80, 1, TK, false><<<dim3(BATCH * TK / 64, 2), 256>>>(kh1, kW2, kb2, kenc);

    // queries path
    conv1d_gemm<80,  160, 3, TQ, true ><<<dim3(BATCH * TQ / 64, 3), 256>>>(queries, qW1, qb1, qh1);
    conv1d_gemm<160,  80, 1, TQ, true ><<<dim3(BATCH * TQ / 64, 2), 256>>>(qh1,     qW2, qb2, qh2);
    conv1d_gemm<80,   80, 1, TQ, false><<<dim3(BATCH * TQ / 64, 2), 256>>>(qh2,     qW3, qb3, qenc);

    // fused attention
    const int smem = (80 * TK + 32 * 81 + TK) * (int)sizeof(float);
    cudaFuncSetAttribute(attn_kernel, cudaFuncAttributeMaxDynamicSharedMemorySize, smem);
    attn_kernel<<<dim3(TQ / 32, BATCH), 256, smem>>>(qenc, kenc, prior, mask, attn_out, logp_out);
}